// round 16
// baseline (speedup 1.0000x reference)
#include <cuda_runtime.h>
#include <cstddef>

// Problem constants
#define TT 512
#define BB 256
#define FF 64
#define UU 128
#define NR 2              // batch rows per CTA
#define NCTA (BB / NR)    // 128 CTAs
#define NTHREADS 512

// Output layout: out_seq (T,B,5F) then hT (B,U) then tsT (B,F) then dtT (B,F)
#define OFF_H  ((size_t)TT * BB * 5 * FF)
#define OFF_TS (OFF_H + (size_t)BB * UU)
#define OFF_DT (OFF_TS + (size_t)BB * FF)

// scratch regions (float offsets). Each slot = 8 floats: row0 float4 | row1 float4.
#define SCR_S0 0        // 2048: S0 partials (P). Reused late in step for J (rg@u_upd).
#define SCR_WD 2048     // 2048: w_delta partials (P)
#define SCR_F  4096     // 2048: dh@u_update / dh@u_reset partials (P)
#define SCR_B  6144     // 1536: gate m-half (Q phase1) + c-half accum (Q H): (gm,kh,uq)
#define SCR_D  7680     // 1024: z_corr partials (Q)
#define SCR_E  8704     // 512:  w_concat m-half (Q)
#define SCR_E2 9216     // 1024: w_concat decay-half (Q)
#define SCR_TOTAL 10240

struct Smem {
    float u_upd[UU * UU];     // u_update  128x128 (P: F gate0, J)
    float w_upd[UU * UU];     // w_update  128x128 (Q: B m-half, H c-half)
    float bctl[FF];
    float bcorr[FF];
    // row-interleaved state: [dim] -> {row0, row1}
    float2 h2[UU];
    float2 dh2[UU];
    float2 decay2[UU];
    float2 rg2[UU];
    float2 zbuf2[UU];
    float2 ts2[FF];
    float2 dtv2[FF];
    float2 xreg2[FF];
    float2 xcur2[FF];
    float2 mm2[FF];
    float2 cc2[FF];
    float xbuf[2][NR][5 * FF]; // double-buffered inputs
    float scratch[SCR_TOTAL];
};

__device__ __forceinline__ float sigmoidf_(float x) {
    return 1.0f / (1.0f + expf(-x));
}

#define FMA8(w4, a2, p0, p1)                                            \
    p0.x += (w4).x * (a2).x; p0.y += (w4).y * (a2).x;                   \
    p0.z += (w4).z * (a2).x; p0.w += (w4).w * (a2).x;                   \
    p1.x += (w4).x * (a2).y; p1.y += (w4).y * (a2).y;                   \
    p1.z += (w4).z * (a2).y; p1.w += (w4).w * (a2).y;

#define BARS(id, count) asm volatile("bar.sync %0, %1;"   :: "r"(id), "r"(count) : "memory")
#define BARA(id, count) asm volatile("bar.arrive %0, %1;" :: "r"(id), "r"(count) : "memory")

__global__ void __launch_bounds__(NTHREADS, 1)
padd_gru_kernel(const float* __restrict__ inputs,
                const float* __restrict__ h0,
                const float* __restrict__ ts0,
                const float* __restrict__ dt0,
                const float* __restrict__ w_regression,
                const float* __restrict__ b_regression,
                const float* __restrict__ w_controleur,
                const float* __restrict__ b_controleur,
                const float* __restrict__ w_delta,
                const float* __restrict__ b_delta,
                const float* __restrict__ w_value_mask,
                const float* __restrict__ b_value_mask,
                const float* __restrict__ w_corr,
                const float* __restrict__ b_corr,
                const float* __restrict__ w_concat,
                const float* __restrict__ b_concat,
                const float* __restrict__ u_update,
                const float* __restrict__ w_update,
                const float* __restrict__ b_update,
                const float* __restrict__ u_reset,
                const float* __restrict__ w_reset,
                const float* __restrict__ b_reset,
                float* __restrict__ out)
{
    extern __shared__ float smem_raw[];
    Smem& S = *reinterpret_cast<Smem*>(smem_raw);
    const int tid = threadIdx.x;
    const int b0 = blockIdx.x * NR;

    // ---- prologue: cache u_update + w_update in smem ----
    for (int i = tid; i < UU * UU; i += NTHREADS) S.u_upd[i] = u_update[i];
    for (int i = tid; i < UU * UU; i += NTHREADS) S.w_upd[i] = w_update[i];
    for (int i = tid; i < FF; i += NTHREADS) { S.bctl[i] = b_controleur[i]; S.bcorr[i] = b_corr[i]; }

    // ---- state init (row-interleaved) ----
    if (tid < UU) {
        S.h2[tid] = make_float2(h0[(size_t)b0 * UU + tid], h0[(size_t)(b0 + 1) * UU + tid]);
    } else if (tid < UU + FF) {
        int f = tid - UU;
        S.ts2[f]  = make_float2(ts0[(size_t)b0 * FF + f], ts0[(size_t)(b0 + 1) * FF + f]);
        S.dtv2[f] = make_float2(dt0[(size_t)b0 * FF + f], dt0[(size_t)(b0 + 1) * FF + f]);
    }
    // prefetch x for t=0
    if (tid < 320) {
        int r = tid / 160, c2 = tid - r * 160;
        const float2* src = reinterpret_cast<const float2*>(inputs + ((size_t)(b0 + r) * TT) * (5 * FF));
        reinterpret_cast<float2*>(&S.xbuf[0][0][0])[r * 160 + c2] = src[c2];
    }

    const float breg = b_regression[0];
    const float bdel = b_delta[0];
    const float bvm  = b_value_mask[0];
    const float bcc  = b_concat[0];
    const float bupd = b_update[0];
    const float brst = b_reset[0];
    __syncthreads();

    float* const ts_s   = reinterpret_cast<float*>(S.ts2);
    float* const dtv_s  = reinterpret_cast<float*>(S.dtv2);
    float* const xreg_s = reinterpret_cast<float*>(S.xreg2);
    float* const xcur_s = reinterpret_cast<float*>(S.xcur2);
    float* const mm_s   = reinterpret_cast<float*>(S.mm2);
    float* const cc_s   = reinterpret_cast<float*>(S.cc2);
    float* const dec_s  = reinterpret_cast<float*>(S.decay2);
    float* const dh_s   = reinterpret_cast<float*>(S.dh2);
    float* const rg_s   = reinterpret_cast<float*>(S.rg2);
    float* const zb_s   = reinterpret_cast<float*>(S.zbuf2);
    float* const h_s    = reinterpret_cast<float*>(S.h2);

    for (int t = 0; t < TT; ++t) {
        if (tid < 256) {
            // ================= GROUP P (warps 0-7): recurrence critical path =================
            const int t7 = tid & 127;

            // --- P1: S0 partials: h @ w_regression / w_controleur ---
            {
                const int m = tid >> 7;                 // 0: regression, 1: controleur
                const int fq = t7 & 15, ksl = t7 >> 4;  // 16 quads x 8 kslices(16k)
                const float* W = m ? w_controleur : w_regression;
                float4 p0 = make_float4(0.f, 0.f, 0.f, 0.f);
                float4 p1 = make_float4(0.f, 0.f, 0.f, 0.f);
#pragma unroll
                for (int i = 0; i < 16; ++i) {
                    int k = ksl * 16 + i;
                    float4 w = *reinterpret_cast<const float4*>(&W[(size_t)k * FF + fq * 4]);
                    float2 a = S.h2[k];
                    FMA8(w, a, p0, p1);
                }
                float* dst = &S.scratch[SCR_S0 + ((m * 8 + ksl) * 16 + fq) * 8];
                *reinterpret_cast<float4*>(dst)     = p0;
                *reinterpret_cast<float4*>(dst + 4) = p1;
            }
            BARS(1, 256);

            // --- P2: C1 elementwise combine (threads 0..127) ---
            if (tid < 128) {
                const int r = tid >> 6, f = tid & 63;
                const int fq = f >> 2, c = f & 3;
                float xr = breg, tvs = S.bctl[f];
#pragma unroll
                for (int ksl = 0; ksl < 8; ++ksl) {
                    xr  += S.scratch[SCR_S0 + ((ksl) * 16 + fq) * 8 + r * 4 + c];
                    tvs += S.scratch[SCR_S0 + ((8 + ksl) * 16 + fq) * 8 + r * 4 + c];
                }
                float tv = fabsf(tvs);
                const float* xb = S.xbuf[t & 1][r];
                float ti_in = xb[f];
                float x_in  = xb[FF + f];
                float m     = xb[2 * FF + f];
                float dt_in = xb[3 * FF + f];
                float pad   = xb[4 * FF + f];
                float pts = ts_s[f * 2 + r], pdt = dtv_s[f * 2 + r];
                float cand = pts + tv;
                float ti = pad * ti_in + (1.f - pad) * cand;
                ti = (ti <= 100.0f) ? ti : pts;
                float dgen = (cand <= 100.0f) ? tv : pdt;
                float ndt = pad * dt_in + (1.f - pad) * dgen;
                float xc = m * x_in + (1.f - m) * xr;
                ts_s[f * 2 + r]   = ti;
                dtv_s[f * 2 + r]  = ndt;
                xreg_s[f * 2 + r] = xr;
                xcur_s[f * 2 + r] = xc;
                mm_s[f * 2 + r]   = m;
                size_t ob = ((size_t)t * BB + (b0 + r)) * (5 * FF);
                out[ob + f]          = xr;
                out[ob + 3 * FF + f] = ti;
                out[ob + 4 * FF + f] = ndt;
            }
            BARA(2, 512);   // hand xcur/mm/xreg to Q
            BARS(4, 256);   // P-internal: dtv visible

            // --- P3: w_delta partials ---
            {
                const int uq = tid & 31, ksl = tid >> 5;   // 0..7, 8 k each
                float4 p0 = make_float4(0.f, 0.f, 0.f, 0.f);
                float4 p1 = make_float4(0.f, 0.f, 0.f, 0.f);
#pragma unroll
                for (int i = 0; i < 8; ++i) {
                    int k = ksl * 8 + i;
                    float4 w = *reinterpret_cast<const float4*>(&w_delta[(size_t)k * UU + uq * 4]);
                    float2 a = S.dtv2[k];
                    FMA8(w, a, p0, p1);
                }
                float* dst = &S.scratch[SCR_WD + (ksl * 32 + uq) * 8];
                *reinterpret_cast<float4*>(dst)     = p0;
                *reinterpret_cast<float4*>(dst + 4) = p1;
            }
            BARS(3, 256);

            // --- P4: decay + dh ---
            {
                const int r = tid >> 7, u = tid & 127;
                const int uq = u >> 2, c = u & 3;
                float d = bdel;
#pragma unroll
                for (int ksl = 0; ksl < 8; ++ksl)
                    d += S.scratch[SCR_WD + (ksl * 32 + uq) * 8 + r * 4 + c];
                float dec = expf(-fmaxf(d, 0.f));
                dec_s[u * 2 + r] = dec;
                dh_s[u * 2 + r]  = dec * h_s[u * 2 + r];
            }
            BARA(5, 384);   // hand decay to Q-high
            BARS(4, 256);   // P-internal: dh visible

            // --- P5: F = dh @ u_update (smem) / dh @ u_reset (L2) ---
            {
                const int gate = tid >> 7;
                const int uq = t7 & 31, ksl = t7 >> 5;  // 0..3, 32 k each
                float4 p0 = make_float4(0.f, 0.f, 0.f, 0.f);
                float4 p1 = make_float4(0.f, 0.f, 0.f, 0.f);
                if (gate == 0) {
#pragma unroll 8
                    for (int i = 0; i < 32; ++i) {
                        int k = ksl * 32 + i;
                        float4 w = *reinterpret_cast<const float4*>(&S.u_upd[k * UU + uq * 4]);
                        float2 a = S.dh2[k];
                        FMA8(w, a, p0, p1);
                    }
                } else {
#pragma unroll 8
                    for (int i = 0; i < 32; ++i) {
                        int k = ksl * 32 + i;
                        float4 w = *reinterpret_cast<const float4*>(&u_reset[(size_t)k * UU + uq * 4]);
                        float2 a = S.dh2[k];
                        FMA8(w, a, p0, p1);
                    }
                }
                float* dst = &S.scratch[SCR_F + ((gate * 4 + ksl) * 32 + uq) * 8];
                *reinterpret_cast<float4*>(dst)     = p0;
                *reinterpret_cast<float4*>(dst + 4) = p1;
            }
            BARS(6, 512);   // wait Q's B+H scratch (and publish F)

            // --- P6: z, r combine; rg = r*dh (both rows per thread) ---
            {
                const int g = tid >> 7;     // 0=update(z), 1=reset(r)
                const int u = tid & 127;
                const int uq = u >> 2, c = u & 3;
                float bias = g ? brst : bupd;
#pragma unroll
                for (int r = 0; r < 2; ++r) {
                    float s = bias;
#pragma unroll
                    for (int ksl = 0; ksl < 4; ++ksl)
                        s += S.scratch[SCR_F + ((g * 4 + ksl) * 32 + uq) * 8 + r * 4 + c];
#pragma unroll
                    for (int kh = 0; kh < 2; ++kh)
                        s += S.scratch[SCR_B + ((g * 2 + kh) * 32 + uq) * 8 + r * 4 + c];
                    float sg = sigmoidf_(s);
                    if (g == 0) zb_s[u * 2 + r] = sg;
                    else        rg_s[u * 2 + r] = sg * dh_s[u * 2 + r];
                }
            }
            BARS(1, 256);

            // --- P7: J = rg @ u_update partials (reuse SCR_S0) ---
            {
                const int uq = tid & 31, ksl = tid >> 5;  // 0..7, 16 k each
                float4 p0 = make_float4(0.f, 0.f, 0.f, 0.f);
                float4 p1 = make_float4(0.f, 0.f, 0.f, 0.f);
#pragma unroll 8
                for (int i = 0; i < 16; ++i) {
                    int k = ksl * 16 + i;
                    float4 w = *reinterpret_cast<const float4*>(&S.u_upd[k * UU + uq * 4]);
                    float2 a = S.rg2[k];
                    FMA8(w, a, p0, p1);
                }
                float* dst = &S.scratch[SCR_S0 + (ksl * 32 + uq) * 8];
                *reinterpret_cast<float4*>(dst)     = p0;
                *reinterpret_cast<float4*>(dst + 4) = p1;
            }
            BARS(3, 256);

            // --- P8: h_hat combine + h update ---
            {
                const int r = tid >> 7, u = tid & 127;
                const int uq = u >> 2, c = u & 3;
                float s = bvm;
#pragma unroll
                for (int ksl = 0; ksl < 8; ++ksl)
                    s += S.scratch[SCR_S0 + (ksl * 32 + uq) * 8 + r * 4 + c];
#pragma unroll
                for (int kh = 0; kh < 2; ++kh)
                    s += S.scratch[SCR_B + ((4 + kh) * 32 + uq) * 8 + r * 4 + c];
                float hh = tanhf(s);
                float z = zb_s[u * 2 + r];
                float hv = h_s[u * 2 + r];
                h_s[u * 2 + r] = (1.f - z) * hv + z * hh;
            }
        } else {
            // ================= GROUP Q (warps 8-15): mask/correlation dataflow =================
            const int tq = tid - 256;

            // --- Q1: prefetch x_{t+1} + m-half gate GEMVs + w_concat m-half ---
            if (t + 1 < TT) {
                const float2* src0 = reinterpret_cast<const float2*>(
                    inputs + ((size_t)b0 * TT + (t + 1)) * (5 * FF));
                const float2* src1 = reinterpret_cast<const float2*>(
                    inputs + ((size_t)(b0 + 1) * TT + (t + 1)) * (5 * FF));
                float2* dst = reinterpret_cast<float2*>(&S.xbuf[(t + 1) & 1][0][0]);
                {
                    int i = tq;                 // 0..255
                    dst[i] = (i < 160) ? src0[i] : src1[i - 160];
                }
                if (tq < 64) {
                    int i = tq + 256;           // 256..319
                    dst[i] = src1[i - 160];
                }
            }
            {
                const float* xb0 = &S.xbuf[t & 1][0][2 * FF];
                const float* xb1 = &S.xbuf[t & 1][1][2 * FF];
                if (tq < 192) {
                    const int gm = tq >> 6;            // 0:w_upd 1:w_reset 2:w_value_mask
                    const int t6 = tq & 63;
                    const int uq = t6 & 31, kh = t6 >> 5;   // 2 khalves x 32 k
                    float4 p0 = make_float4(0.f, 0.f, 0.f, 0.f);
                    float4 p1 = make_float4(0.f, 0.f, 0.f, 0.f);
                    if (gm == 0) {
#pragma unroll 8
                        for (int i = 0; i < 32; ++i) {
                            int k = kh * 32 + i;
                            float4 w = *reinterpret_cast<const float4*>(&S.w_upd[(FF + k) * UU + uq * 4]);
                            float2 a = make_float2(xb0[k], xb1[k]);
                            FMA8(w, a, p0, p1);
                        }
                    } else {
                        const float* W = (gm == 1) ? w_reset : w_value_mask;
#pragma unroll 8
                        for (int i = 0; i < 32; ++i) {
                            int k = kh * 32 + i;
                            float4 w = *reinterpret_cast<const float4*>(&W[(size_t)(FF + k) * UU + uq * 4]);
                            float2 a = make_float2(xb0[k], xb1[k]);
                            FMA8(w, a, p0, p1);
                        }
                    }
                    float* dst = &S.scratch[SCR_B + ((gm * 2 + kh) * 32 + uq) * 8];
                    *reinterpret_cast<float4*>(dst)     = p0;
                    *reinterpret_cast<float4*>(dst + 4) = p1;
                } else {
                    const int tE = tq - 192;
                    const int fq = tE & 15, kq = tE >> 4;   // 0..3, 16 k each
                    float4 p0 = make_float4(0.f, 0.f, 0.f, 0.f);
                    float4 p1 = make_float4(0.f, 0.f, 0.f, 0.f);
#pragma unroll 8
                    for (int i = 0; i < 16; ++i) {
                        int k = kq * 16 + i;
                        float4 w = *reinterpret_cast<const float4*>(&w_concat[(size_t)k * FF + fq * 4]);
                        float2 a = make_float2(xb0[k], xb1[k]);
                        FMA8(w, a, p0, p1);
                    }
                    float* dst = &S.scratch[SCR_E + (kq * 16 + fq) * 8];
                    *reinterpret_cast<float4*>(dst)     = p0;
                    *reinterpret_cast<float4*>(dst + 4) = p1;
                }
            }
            BARS(2, 512);   // wait P's C1 (xcur/mm/xreg ready)

            // --- Q2: z_corr (warps 8-11) || decay-half of w_concat (warps 12-15) ---
            if (tq < 128) {
                const int fq = tq & 15, ksl = tq >> 4;   // 0..7, 8 k each
                float4 p0 = make_float4(0.f, 0.f, 0.f, 0.f);
                float4 p1 = make_float4(0.f, 0.f, 0.f, 0.f);
#pragma unroll
                for (int i = 0; i < 8; ++i) {
                    int k = ksl * 8 + i;
                    float4 w = *reinterpret_cast<const float4*>(&w_corr[(size_t)k * FF + fq * 4]);
                    if ((k >> 2) == fq) reinterpret_cast<float*>(&w)[k & 3] = 0.f;  // off-diag mask
                    float2 a = S.xcur2[k];
                    FMA8(w, a, p0, p1);
                }
                float* dst = &S.scratch[SCR_D + (ksl * 16 + fq) * 8];
                *reinterpret_cast<float4*>(dst)     = p0;
                *reinterpret_cast<float4*>(dst + 4) = p1;
            } else {
                BARS(5, 384);   // wait P's decay
                const int tE = tq - 128;
                const int fq = tE & 15, ksl = tE >> 4;   // 0..7, 16 k each
                float4 p0 = make_float4(0.f, 0.f, 0.f, 0.f);
                float4 p1 = make_float4(0.f, 0.f, 0.f, 0.f);
#pragma unroll 8
                for (int i = 0; i < 16; ++i) {
                    int k = ksl * 16 + i;
                    float4 w = *reinterpret_cast<const float4*>(&w_concat[(size_t)(FF + k) * FF + fq * 4]);
                    float2 a = S.decay2[k];
                    FMA8(w, a, p0, p1);
                }
                float* dst = &S.scratch[SCR_E2 + (ksl * 16 + fq) * 8];
                *reinterpret_cast<float4*>(dst)     = p0;
                *reinterpret_cast<float4*>(dst + 4) = p1;
            }
            BARS(7, 256);

            // --- Q3: G = z_corr combine + beta + c (warps 8-11) ---
            if (tq < 128) {
                const int r = tq >> 6, f = tq & 63;
                const int fq = f >> 2, c = f & 3;
                float zc = S.bcorr[f];
#pragma unroll
                for (int ksl = 0; ksl < 8; ++ksl)
                    zc += S.scratch[SCR_D + (ksl * 16 + fq) * 8 + r * 4 + c];
                float bsum = bcc;
#pragma unroll
                for (int kq = 0; kq < 4; ++kq)
                    bsum += S.scratch[SCR_E + (kq * 16 + fq) * 8 + r * 4 + c];
#pragma unroll
                for (int ksl = 0; ksl < 8; ++ksl)
                    bsum += S.scratch[SCR_E2 + (ksl * 16 + fq) * 8 + r * 4 + c];
                float beta = sigmoidf_(bsum);
                float xr = xreg_s[f * 2 + r];
                float ct = beta * zc + (1.f - beta) * xr;
                float m = mm_s[f * 2 + r];
                float cv = m * xcur_s[f * 2 + r] + (1.f - m) * ct;
                cc_s[f * 2 + r] = cv;
                size_t ob = ((size_t)t * BB + (b0 + r)) * (5 * FF);
                out[ob + FF + f]     = zc;
                out[ob + 2 * FF + f] = cv;
            }
            BARS(8, 256);

            // --- Q4: H = c-half of w_update/w_reset/w_value_mask, accumulate into SCR_B ---
            if (tq < 192) {
                const int gm = tq >> 6;
                const int t6 = tq & 63;
                const int uq = t6 & 31, kh = t6 >> 5;
                float4 p0 = make_float4(0.f, 0.f, 0.f, 0.f);
                float4 p1 = make_float4(0.f, 0.f, 0.f, 0.f);
                if (gm == 0) {
#pragma unroll 8
                    for (int i = 0; i < 32; ++i) {
                        int k = kh * 32 + i;
                        float4 w = *reinterpret_cast<const float4*>(&S.w_upd[k * UU + uq * 4]);
                        float2 a = S.cc2[k];
                        FMA8(w, a, p0, p1);
                    }
                } else {
                    const float* W = (gm == 1) ? w_reset : w_value_mask;
#pragma unroll 8
                    for (int i = 0; i < 32; ++i) {
                        int k = kh * 32 + i;
                        float4 w = *reinterpret_cast<const float4*>(&W[(size_t)k * UU + uq * 4]);
                        float2 a = S.cc2[k];
                        FMA8(w, a, p0, p1);
                    }
                }
                float* dst = &S.scratch[SCR_B + ((gm * 2 + kh) * 32 + uq) * 8];
                float4 q0 = *reinterpret_cast<float4*>(dst);
                float4 q1 = *reinterpret_cast<float4*>(dst + 4);
                q0.x += p0.x; q0.y += p0.y; q0.z += p0.z; q0.w += p0.w;
                q1.x += p1.x; q1.y += p1.y; q1.z += p1.z; q1.w += p1.w;
                *reinterpret_cast<float4*>(dst)     = q0;
                *reinterpret_cast<float4*>(dst + 4) = q1;
            }
            BARA(6, 512);   // publish B+H to P
        }
        __syncthreads();
    }

    // ---- epilogue: final carries ----
    if (tid < 256) {
        const int r = tid >> 7, u = tid & 127;
        out[OFF_H + (size_t)(b0 + r) * UU + u] = h_s[u * 2 + r];
    }
    if (tid < 128) {
        const int r = tid >> 6, f = tid & 63;
        out[OFF_TS + (size_t)(b0 + r) * FF + f] = ts_s[f * 2 + r];
        out[OFF_DT + (size_t)(b0 + r) * FF + f] = dtv_s[f * 2 + r];
    }
}

extern "C" void kernel_launch(void* const* d_in, const int* in_sizes, int n_in,
                              void* d_out, int out_size) {
    const float* inputs        = (const float*)d_in[0];
    const float* h0            = (const float*)d_in[1];
    const float* ts0           = (const float*)d_in[2];
    const float* dt0           = (const float*)d_in[3];
    const float* w_regression  = (const float*)d_in[4];
    const float* b_regression  = (const float*)d_in[5];
    const float* w_controleur  = (const float*)d_in[6];
    const float* b_controleur  = (const float*)d_in[7];
    const float* w_delta       = (const float*)d_in[8];
    const float* b_delta       = (const float*)d_in[9];
    const float* w_value_mask  = (const float*)d_in[10];
    const float* b_value_mask  = (const float*)d_in[11];
    const float* w_corr        = (const float*)d_in[12];
    const float* b_corr        = (const float*)d_in[13];
    const float* w_concat      = (const float*)d_in[14];
    const float* b_concat      = (const float*)d_in[15];
    const float* u_update      = (const float*)d_in[16];
    const float* w_update      = (const float*)d_in[17];
    const float* b_update      = (const float*)d_in[18];
    const float* u_reset       = (const float*)d_in[19];
    const float* w_reset       = (const float*)d_in[20];
    const float* b_reset       = (const float*)d_in[21];
    float* out = (float*)d_out;

    cudaFuncSetAttribute(padd_gru_kernel,
                         cudaFuncAttributeMaxDynamicSharedMemorySize,
                         (int)sizeof(Smem));
    padd_gru_kernel<<<NCTA, NTHREADS, sizeof(Smem)>>>(
        inputs, h0, ts0, dt0,
        w_regression, b_regression, w_controleur, b_controleur,
        w_delta, b_delta, w_value_mask, b_value_mask,
        w_corr, b_corr, w_concat, b_concat,
        u_update, w_update, b_update,
        u_reset, w_reset, b_reset,
        out);
}